// round 16
// baseline (speedup 1.0000x reference)
#include <cuda_runtime.h>

#define N_CELLS 776
#define N_ANCHORS 3
#define N_CH 7
#define CONF_THRESH 0.8f
#define NO_OBJECT 0.5f

#define CELL_F      (N_ANCHORS * N_CH)          // 21 floats/cell
#define TOTAL_F     (N_CELLS * CELL_F)          // 16296 floats
#define TOTAL_V4    (TOTAL_F / 4)               // 4074 float4
#define CELLS_PER_WARP  32
#define N_CTAS      ((N_CELLS + CELLS_PER_WARP - 1) / CELLS_PER_WARP)  // 25
#define WARP_F      (CELLS_PER_WARP * CELL_F)   // 672 floats
#define WARP_V4     (WARP_F / 4)                // 168 float4

// Packed accumulator: bits [0,56) = fixed-point sum (scale 2^38, all partials
// >= 0), bits [56,64) = arrival count (25 warps). Zero-init at load; the last
// arriving warp stores the result and resets for the next graph replay.
// Integer adds are commutative -> bitwise-deterministic result.
#define COUNT_ONE   (1ULL << 56)
#define SUM_MASK    (COUNT_ONE - 1ULL)
__device__ unsigned long long g_accum;

__device__ __forceinline__ float sqrt_approx(float x) {
    float y;
    asm("sqrt.approx.f32 %0, %1;" : "=f"(y) : "f"(x));
    return y;
}

__global__ __launch_bounds__(32, 1)
void yolo_loss_kernel(const float* __restrict__ pred,
                      const float* __restrict__ label,
                      float* __restrict__ out) {
    // One warp per CTA: minimal per-SM L1tex queue depth, no block barriers.
    __shared__ float sh[WARP_F];   // 2688 B

    const int lane = threadIdx.x;
    const int bid  = blockIdx.x;   // == global warp id, 0..24

    // Label loads first so they overlap the pred staging round trip.
    const float lx = __ldg(&label[0]);
    const float ly = __ldg(&label[1]);
    const float lw = __ldg(&label[2]);
    const float lh = __ldg(&label[3]);
    const float lc = __ldg(&label[4]);
    const float l5 = __ldg(&label[5]);
    const float l6 = __ldg(&label[6]);

    // ---- stage this warp's 32 cells into smem (coalesced float4) ----
    {
        const float4* __restrict__ pv = (const float4*)pred;
        float4* sv = (float4*)sh;
        const int base = bid * WARP_V4;
        #pragma unroll
        for (int i = 0; i < 6; i++) {            // 6*32 = 192 >= 168
            const int li = lane + i * 32;
            if (li < WARP_V4 && base + li < TOTAL_V4)
                sv[li] = pv[base + li];
        }
    }

    const float area_b = fabsf(lw * lh);
    const float sqlx = sqrt_approx(lx);
    const float sqly = sqrt_approx(ly);

    __syncwarp();

    // ---- per-cell loss ----
    float local = 0.0f;
    const int cell = bid * CELLS_PER_WARP + lane;
    if (cell < N_CELLS) {
        const float* c = sh + lane * CELL_F;   // stride 21 words: conflict-free

        float v[CELL_F];
        #pragma unroll
        for (int i = 0; i < CELL_F; i++) v[i] = c[i];

        float inter[N_ANCHORS], den[N_ANCHORS];
        #pragma unroll
        for (int a = 0; a < N_ANCHORS; a++) {
            const float px = v[a * N_CH + 0];
            const float py = v[a * N_CH + 1];
            const float pw = v[a * N_CH + 2];
            const float ph = v[a * N_CH + 3];
            const float ax = fmaxf(px - pw * 0.5f, lx - lw * 0.5f);
            const float ay = fmaxf(py - ph * 0.5f, ly - lh * 0.5f);
            const float bx = fminf(px + pw * 0.5f, lx + lw * 0.5f);
            const float by = fminf(py + ph * 0.5f, ly + lh * 0.5f);
            const float in = fabsf(fmaxf(bx - ax, 0.0f) * fmaxf(by - ay, 0.0f));
            inter[a] = in;
            den[a] = fabsf(pw * ph) + area_b - in;   // union area > 0
        }

        // Division-free argmax, strict > keeps first max (jnp.argmax).
        int best = 0;
        if (inter[1] * den[0] > inter[0] * den[1]) best = 1;
        if (inter[2] * den[best] > inter[best] * den[2]) best = 2;

        const float b0 = v[best * N_CH + 0];
        const float b1 = v[best * N_CH + 1];
        const float b4 = v[best * N_CH + 4];
        const float b5 = v[best * N_CH + 5];
        const float b6 = v[best * N_CH + 6];

        const float dx = lx - b0;
        const float dy = ly - b1;
        const float xy_loss = dx * dx + dy * dy;

        // Reference uses label[0]/label[1], best[:,0]/best[:,1] in the sqrt
        // terms — replicated verbatim.
        const float swx = sqlx - sqrt_approx(b0);
        const float swy = sqly - sqrt_approx(b1);
        const float wh_loss = swx * swx + swy * swy;

        const bool has_obj = b4 > CONF_THRESH;
        float class_loss = 0.0f;
        if (has_obj) {
            const float d5 = l5 - b5;
            const float d6 = l6 - b6;
            class_loss = d5 * d5 + d6 * d6;
        }
        const float dc = lc - b4;
        const float conf_sq = dc * dc;
        const float conf_loss = has_obj ? conf_sq : NO_OBJECT * conf_sq;

        local = xy_loss + wh_loss + class_loss + conf_loss;
    }

    // ---- intra-warp reduce (fixed order -> deterministic) ----
    #pragma unroll
    for (int off = 16; off > 0; off >>= 1)
        local += __shfl_down_sync(0xFFFFFFFFu, local, off);

    // ---- one packed atomic per warp; last of 25 arrivals finishes ----
    if (lane == 0) {
        // local >= 0 always. f32 fixed-point (2^38): quantization rel-err
        // ~6e-8 on the final sum, far under the 1e-3 threshold, and the
        // f32 convert is ~80cy cheaper than the fp64 path before ATOMG.
        const unsigned long long fixed =
            (unsigned long long)__float2ll_rn(local * 0x1p38f);
        const unsigned long long packed = fixed + COUNT_ONE;
        const unsigned long long old = atomicAdd(&g_accum, packed);
        const unsigned long long now = old + packed;
        if ((now >> 56) == (unsigned long long)N_CTAS) {
            // Last warp: full sum already in-register. Store & reset.
            const float total =
                (float)((double)(long long)(now & SUM_MASK) * 0x1p-38);
            out[0] = total;
            atomicExch(&g_accum, 0ULL);   // ready for next graph replay
        }
    }
}

extern "C" void kernel_launch(void* const* d_in, const int* in_sizes, int n_in,
                              void* d_out, int out_size) {
    const float* pred  = (const float*)d_in[0];
    const float* label = (const float*)d_in[1];
    float* out = (float*)d_out;
    yolo_loss_kernel<<<N_CTAS, 32>>>(pred, label, out);
}